// round 1
// baseline (speedup 1.0000x reference)
#include <cuda_runtime.h>

// Problem constants (fixed by reference_code)
#define LSEQ 8192
#define BATCH 32
#define CIN 7
#define KER 73       // 512 // 7
#define DM 512
#define RT 16        // output rows (n) per block tile
#define WIN (RT + 17) // x window rows needed: offsets -1..16 around the tile

// out[b, n, c*73+k] = conv_b[k] + sum_{j=0..17} W2[k][j] * x[b, n+1-j, c]
//   W2[k][j] = conv_w[k][ (j/3)*3 + (2 - j%3) ]
// valid only where the conv position p = n-1+t satisfies p >= 15 (M*TAO),
// with circular wrap of p at the sequence ends. Interior rows (16..L-2)
// need no predicates; first/last tiles take the generic slow path.

__global__ __launch_bounds__(512)
void tokemb_kernel(const float* __restrict__ x,
                   const float* __restrict__ conv_w,
                   const float* __restrict__ conv_b,
                   const float* __restrict__ left_w,
                   const float* __restrict__ left_b,
                   float* __restrict__ out)
{
    const int d  = threadIdx.x;          // output channel 0..511
    const int n0 = blockIdx.x * RT;      // first output row of this tile
    const int b  = blockIdx.y;

    // Per-thread channel / weights / bias
    const bool main_ch = (d < CIN * KER);            // d < 511
    const int  c    = main_ch ? (d / KER) : (CIN - 1);
    const float* wsrc = main_ch ? (conv_w + (d % KER) * 18) : left_w;
    const float bias  = main_ch ? conv_b[d % KER] : left_b[0];

    // Reorder weights into offset form: wreg[j] multiplies x[n+1-j]
    float wreg[18];
    #pragma unroll
    for (int j = 0; j < 18; ++j)
        wreg[j] = wsrc[(j / 3) * 3 + 2 - (j % 3)];

    const float* xb  = x + (size_t)b * LSEQ * CIN;
    float* outp      = out + ((size_t)(b * LSEQ + n0)) * DM + d;

    const bool fast = (n0 >= 16) && (n0 + RT <= LSEQ - 1);

    __shared__ float xs[WIN * CIN];

    if (fast) {
        // Stage x[b, n0-16 .. n0+RT, :] (33 rows x 7 ch) into smem, coalesced.
        const float* src = xb + (n0 - 16) * CIN;
        for (int i = threadIdx.x; i < WIN * CIN; i += blockDim.x)
            xs[i] = src[i];
        __syncthreads();

        // Pull this thread's channel column into a register window.
        float xr[WIN];
        #pragma unroll
        for (int i = 0; i < WIN; ++i)
            xr[i] = xs[i * CIN + c];

        // xr[i] = x[b, n0-16+i, c]; output n = n0+nl uses x[n+1-j] = xr[nl+17-j]
        #pragma unroll
        for (int nl = 0; nl < RT; ++nl) {
            float acc = bias;
            #pragma unroll
            for (int j = 0; j < 18; ++j)
                acc = fmaf(wreg[j], xr[nl + 17 - j], acc);
            outp[nl * DM] = acc;
        }
    } else {
        // Generic path: explicit wrap + validity per conv tap. Only 2 tiles
        // per batch row (64 / 16384 blocks) land here.
        for (int nl = 0; nl < RT; ++nl) {
            const int n = n0 + nl;
            float acc = bias;
            #pragma unroll
            for (int t = 0; t < 3; ++t) {
                int p = n - 1 + t;
                if (p < 0)      p += LSEQ;   // circular pad left
                if (p >= LSEQ)  p -= LSEQ;   // circular pad right
                if (p >= 15) {               // delay-embedding validity (M*TAO)
                    #pragma unroll
                    for (int m = 0; m < 6; ++m)
                        acc = fmaf(wreg[3 * m + 2 - t],
                                   xb[(p - 3 * m) * CIN + c], acc);
                }
            }
            outp[nl * DM] = acc;
        }
    }
}

extern "C" void kernel_launch(void* const* d_in, const int* in_sizes, int n_in,
                              void* d_out, int out_size)
{
    const float* x      = (const float*)d_in[0];
    const float* conv_w = (const float*)d_in[1];
    const float* conv_b = (const float*)d_in[2];
    const float* left_w = (const float*)d_in[3];
    const float* left_b = (const float*)d_in[4];
    float* out = (float*)d_out;

    dim3 grid(LSEQ / RT, BATCH);   // (512, 32) blocks
    tokemb_kernel<<<grid, 512>>>(x, conv_w, conv_b, left_w, left_b, out);
}

// round 2
// speedup vs baseline: 2.0851x; 2.0851x over previous
#include <cuda_runtime.h>

// Problem constants (fixed by reference_code)
#define LSEQ 8192
#define BATCH 32
#define CIN 7
#define KER 73        // 512 // 7
#define DM 512
#define RT 16         // output rows per tile
#define SL 256        // rows per block strip
#define TILES (SL / RT)       // 16
#define WROWS (SL + RT + 1)   // 273 window rows: strip + 16 back + 1 fwd
#define WELEMS (WROWS * CIN)  // 1911

// out[b, n, c*73+k] = conv_b[k] + sum_{j=0..17} W2[k][j] * x[b, n+1-j, c]
//   W2[k][j] = conv_w[k][ (j/3)*3 + (2 - j%3) ]
// Conv position p = n-1+t contributes only if (after circular wrap) p >= 15.
// Interior rows 16..L-2 are unconditionally valid (fast path).

__global__ __launch_bounds__(512, 2)
void tokemb_kernel(const float* __restrict__ x,
                   const float* __restrict__ conv_w,
                   const float* __restrict__ conv_b,
                   const float* __restrict__ left_w,
                   const float* __restrict__ left_b,
                   float* __restrict__ out)
{
    const int d  = threadIdx.x;          // output channel 0..511
    const int s0 = blockIdx.x * SL;      // strip start row
    const int b  = blockIdx.y;

    // Per-thread channel / weights / bias (loaded ONCE per block)
    const bool main_ch = (d < CIN * KER);            // d < 511
    const int  c    = main_ch ? (d / KER) : (CIN - 1);
    const float* wsrc = main_ch ? (conv_w + (d % KER) * 18) : left_w;
    const float bias  = main_ch ? conv_b[d % KER] : left_b[0];

    float w[18];
    #pragma unroll
    for (int j = 0; j < 18; ++j)
        w[j] = wsrc[(j / 3) * 3 + 2 - (j % 3)];

    const float* xb = x + (size_t)b * LSEQ * CIN;

    // Stage x[b, s0-16 .. s0+SL, :] into smem, flat-coalesced, index-clamped.
    // Clamped (junk) rows are only touched by slow-path tiles, which ignore smem.
    __shared__ float xs[WELEMS];
    {
        const int gbase = (s0 - RT) * CIN;   // may be negative at strip 0
        #pragma unroll
        for (int i = threadIdx.x; i < WELEMS; i += 512) {
            int g = gbase + i;
            g = min(max(g, 0), LSEQ * CIN - 1);
            xs[i] = xb[g];
        }
    }
    __syncthreads();

    float* outp = out + ((size_t)(b * LSEQ + s0)) * DM + d;

    #pragma unroll 1
    for (int t = 0; t < TILES; ++t) {
        const int n0 = s0 + t * RT;
        const bool fast = (n0 >= 16) && (n0 + RT <= LSEQ - 1);
        float* op = outp + t * RT * DM;

        if (fast) {
            // xs local row l = global row s0-16+l; tile t reads l = t*16 .. t*16+32
            const float* xcol = xs + (t * RT) * CIN + c;

            float acc[RT];
            #pragma unroll
            for (int nl = 0; nl < RT; ++nl) acc[nl] = bias;

            // Value-outer: each window value loaded once, fanned into the
            // accumulators it feeds. i, j compile-time => static reg indexing,
            // LDS at immediate offsets.
            #pragma unroll
            for (int i = 0; i < RT + 17; ++i) {
                const float xv = xcol[i * CIN];
                #pragma unroll
                for (int j = 0; j < 18; ++j) {
                    const int nl = i + j - 17;   // output row fed by (i, j)
                    if (nl >= 0 && nl < RT)
                        acc[nl] = fmaf(w[j], xv, acc[nl]);
                }
            }

            #pragma unroll
            for (int nl = 0; nl < RT; ++nl)
                op[nl * DM] = acc[nl];
        } else {
            // Generic path: explicit wrap + validity per conv tap.
            // Only tile 0 of strip 0 and the last tile of the last strip.
            for (int nl = 0; nl < RT; ++nl) {
                const int n = n0 + nl;
                float acc = bias;
                #pragma unroll
                for (int tt = 0; tt < 3; ++tt) {
                    int p = n - 1 + tt;
                    if (p < 0)      p += LSEQ;   // circular pad left
                    if (p >= LSEQ)  p -= LSEQ;   // circular pad right
                    if (p >= 15) {               // delay-embedding validity
                        #pragma unroll
                        for (int m = 0; m < 6; ++m)
                            acc = fmaf(w[3 * m + 2 - tt],
                                       xb[(p - 3 * m) * CIN + c], acc);
                    }
                }
                op[nl * DM] = acc;
            }
        }
    }
}

extern "C" void kernel_launch(void* const* d_in, const int* in_sizes, int n_in,
                              void* d_out, int out_size)
{
    const float* x      = (const float*)d_in[0];
    const float* conv_w = (const float*)d_in[1];
    const float* conv_b = (const float*)d_in[2];
    const float* left_w = (const float*)d_in[3];
    const float* left_b = (const float*)d_in[4];
    float* out = (float*)d_out;

    dim3 grid(LSEQ / SL, BATCH);   // (32, 32) = 1024 blocks
    tokemb_kernel<<<grid, 512>>>(x, conv_w, conv_b, left_w, left_b, out);
}